// round 1
// baseline (speedup 1.0000x reference)
#include <cuda_runtime.h>
#include <cuda_bf16.h>

#define Bq 8
#define Tq 512
#define Cq 768
#define Hq 12
#define Dq 64
#define Lq 12
#define Vq 32000
#define FFq 3072
#define Mq (Bq*Tq)          // 4096
#define BHq (Bq*Hq)         // 96

// ---------------- scratch (device globals; no allocation allowed) ----------
__device__ float g_x  [Mq*Cq];
__device__ float g_q  [Mq*Cq];
__device__ float g_k  [Mq*Cq];
__device__ float g_v  [Mq*Cq];
__device__ float g_att[(size_t)BHq*Tq*Tq];
__device__ float g_m  [BHq*Tq];
__device__ float g_rs [BHq*Tq];
__device__ float g_t1 [Mq*Cq];
__device__ float g_t2 [Mq*Cq];
__device__ float g_ffn[(size_t)Mq*FFq];

// ---------------- embed: x = emb[ids] + pos ---------------------------------
__global__ void embed_kernel(const int* __restrict__ ids,
                             const float* __restrict__ emb,
                             const float* __restrict__ pos,
                             float* __restrict__ x)
{
    int idx = blockIdx.x * blockDim.x + threadIdx.x;
    if (idx >= Mq * Cq) return;
    int m = idx / Cq, c = idx - m * Cq;
    int t = m & (Tq - 1);
    int tok = ids[m];
    x[idx] = emb[(size_t)tok * Cq + c] + pos[(size_t)t * Cq + c];
}

// ---------------- generic GEMM: C = A*B (+bias) (+relu) ---------------------
// 64x64 block tile, 16 k-tile, 256 threads, 4x4 per thread. Exact tiling only.
__global__ void __launch_bounds__(256)
gemm_kernel(const float* __restrict__ A, const float* __restrict__ B,
            const float* __restrict__ bias, float* __restrict__ C,
            int K, int lda, int ldb, int ldc,
            long strideB, long strideC, int relu)
{
    B += (long)blockIdx.z * strideB;
    C += (long)blockIdx.z * strideC;
    const int bm = blockIdx.y * 64;
    const int bn = blockIdx.x * 64;
    __shared__ float As[16][64];   // transposed: As[k][m]
    __shared__ float Bs[16][64];
    const int tid  = threadIdx.x;
    const int tx   = tid & 15;
    const int ty   = tid >> 4;
    const int arow = tid >> 2;            // 0..63
    const int acol = (tid & 3) << 2;      // 0,4,8,12
    const int brow = tid >> 4;            // 0..15
    const int bcol = (tid & 15) << 2;     // 0..60
    float acc[4][4] = {};
    for (int k0 = 0; k0 < K; k0 += 16) {
        float4 av = *reinterpret_cast<const float4*>(&A[(long)(bm + arow) * lda + k0 + acol]);
        As[acol + 0][arow] = av.x;
        As[acol + 1][arow] = av.y;
        As[acol + 2][arow] = av.z;
        As[acol + 3][arow] = av.w;
        *reinterpret_cast<float4*>(&Bs[brow][bcol]) =
            *reinterpret_cast<const float4*>(&B[(long)(k0 + brow) * ldb + bn + bcol]);
        __syncthreads();
#pragma unroll
        for (int kk = 0; kk < 16; kk++) {
            float4 a4 = *reinterpret_cast<const float4*>(&As[kk][ty << 2]);
            float4 b4 = *reinterpret_cast<const float4*>(&Bs[kk][tx << 2]);
            float a[4] = {a4.x, a4.y, a4.z, a4.w};
            float b[4] = {b4.x, b4.y, b4.z, b4.w};
#pragma unroll
            for (int i = 0; i < 4; i++)
#pragma unroll
                for (int j = 0; j < 4; j++)
                    acc[i][j] = fmaf(a[i], b[j], acc[i][j]);
        }
        __syncthreads();
    }
    float bv[4] = {0.f, 0.f, 0.f, 0.f};
    if (bias) {
        float4 t = *reinterpret_cast<const float4*>(&bias[bn + (tx << 2)]);
        bv[0] = t.x; bv[1] = t.y; bv[2] = t.z; bv[3] = t.w;
    }
#pragma unroll
    for (int i = 0; i < 4; i++) {
        float4 o;
        o.x = acc[i][0] + bv[0];
        o.y = acc[i][1] + bv[1];
        o.z = acc[i][2] + bv[2];
        o.w = acc[i][3] + bv[3];
        if (relu) {
            o.x = fmaxf(o.x, 0.f); o.y = fmaxf(o.y, 0.f);
            o.z = fmaxf(o.z, 0.f); o.w = fmaxf(o.w, 0.f);
        }
        *reinterpret_cast<float4*>(&C[(long)(bm + (ty << 2) + i) * ldc + bn + (tx << 2)]) = o;
    }
}

// ---------------- attention scores: att = Q K^T / sqrt(D) -------------------
// grid: (8 k-tiles, 8 q-tiles, 96 bh), block 256
__global__ void __launch_bounds__(256)
scores_kernel(const float* __restrict__ Q, const float* __restrict__ Kt,
              float* __restrict__ att)
{
    int bh = blockIdx.z;
    int b = bh / Hq, h = bh - b * Hq;
    const float* Qp = Q  + (long)b * Tq * Cq + h * Dq;
    const float* Kp = Kt + (long)b * Tq * Cq + h * Dq;
    float* ap = att + (long)bh * Tq * Tq;
    int q0 = blockIdx.y * 64, k0 = blockIdx.x * 64;
    __shared__ float Qs[64][65];
    __shared__ float Ks[64][65];
    int tid = threadIdx.x;
    int lr = tid >> 4;            // 0..15
    int lc = (tid & 15) << 2;     // 0..60
#pragma unroll
    for (int r = 0; r < 4; r++) {
        int row = lr + r * 16;
        float4 qv = *reinterpret_cast<const float4*>(&Qp[(long)(q0 + row) * Cq + lc]);
        Qs[row][lc + 0] = qv.x; Qs[row][lc + 1] = qv.y;
        Qs[row][lc + 2] = qv.z; Qs[row][lc + 3] = qv.w;
        float4 kv = *reinterpret_cast<const float4*>(&Kp[(long)(k0 + row) * Cq + lc]);
        Ks[row][lc + 0] = kv.x; Ks[row][lc + 1] = kv.y;
        Ks[row][lc + 2] = kv.z; Ks[row][lc + 3] = kv.w;
    }
    __syncthreads();
    int tx = tid & 15, ty = tid >> 4;
    float acc[4][4] = {};
#pragma unroll 4
    for (int d = 0; d < 64; d++) {
        float a[4], bb[4];
#pragma unroll
        for (int i = 0; i < 4; i++) a[i]  = Qs[(ty << 2) + i][d];
#pragma unroll
        for (int j = 0; j < 4; j++) bb[j] = Ks[(tx << 2) + j][d];
#pragma unroll
        for (int i = 0; i < 4; i++)
#pragma unroll
            for (int j = 0; j < 4; j++)
                acc[i][j] = fmaf(a[i], bb[j], acc[i][j]);
    }
    const float scale = 0.125f;   // 1/sqrt(64)
#pragma unroll
    for (int i = 0; i < 4; i++) {
        float4 o;
        o.x = acc[i][0] * scale; o.y = acc[i][1] * scale;
        o.z = acc[i][2] * scale; o.w = acc[i][3] * scale;
        *reinterpret_cast<float4*>(&ap[(long)(q0 + (ty << 2) + i) * Tq + k0 + (tx << 2)]) = o;
    }
}

// ---------------- column softmax stats (softmax over q axis!) ---------------
// one block per (b,h); thread k: online max/sum over q of att[:,k]
__global__ void __launch_bounds__(512)
stats_kernel(const float* __restrict__ att, float* __restrict__ mb, float* __restrict__ rsb)
{
    int bh = blockIdx.x;
    int k = threadIdx.x;
    const float* ap = att + (long)bh * Tq * Tq;
    float m = -1e30f, s = 0.f;
    for (int q = 0; q < Tq; q++) {
        float v = ap[(long)q * Tq + k];
        float nm = fmaxf(m, v);
        s = s * __expf(m - nm) + __expf(v - nm);
        m = nm;
    }
    mb[bh * Tq + k]  = m;
    rsb[bh * Tq + k] = 1.f / s;
}

// ---------------- AV: out[q,d] = sum_k exp(att-m_k)*rs_k * V[k,d] -----------
// grid: (8 q-tiles, 96 bh), block 256. Writes concat layout [B,T,C].
__global__ void __launch_bounds__(256)
av_kernel(const float* __restrict__ att, const float* __restrict__ Vv,
          const float* __restrict__ mb, const float* __restrict__ rsb,
          float* __restrict__ out)
{
    int bh = blockIdx.y;
    int b = bh / Hq, h = bh - b * Hq;
    const float* ap = att + (long)bh * Tq * Tq;
    const float* Vp = Vv  + (long)b * Tq * Cq + h * Dq;
    float* op       = out + (long)b * Tq * Cq + h * Dq;
    int q0 = blockIdx.x * 64;
    __shared__ float Ps[64][65];
    __shared__ float Vs[64][68];
    int tid = threadIdx.x;
    int tx = tid & 15, ty = tid >> 4;
    int lr = tid >> 4;            // 0..15
    int lc = (tid & 15) << 2;     // 0..60
    float acc[4][4] = {};
    for (int kt = 0; kt < 8; kt++) {
        int k0 = kt * 64;
        float4 m4 = *reinterpret_cast<const float4*>(&mb [bh * Tq + k0 + lc]);
        float4 r4 = *reinterpret_cast<const float4*>(&rsb[bh * Tq + k0 + lc]);
#pragma unroll
        for (int r = 0; r < 4; r++) {
            int row = lr + r * 16;
            float4 avv = *reinterpret_cast<const float4*>(&ap[(long)(q0 + row) * Tq + k0 + lc]);
            Ps[row][lc + 0] = __expf(avv.x - m4.x) * r4.x;
            Ps[row][lc + 1] = __expf(avv.y - m4.y) * r4.y;
            Ps[row][lc + 2] = __expf(avv.z - m4.z) * r4.z;
            Ps[row][lc + 3] = __expf(avv.w - m4.w) * r4.w;
            float4 vv = *reinterpret_cast<const float4*>(&Vp[(long)(k0 + row) * Cq + lc]);
            *reinterpret_cast<float4*>(&Vs[row][lc]) = vv;
        }
        __syncthreads();
#pragma unroll 4
        for (int kk = 0; kk < 64; kk++) {
            float a[4];
#pragma unroll
            for (int i = 0; i < 4; i++) a[i] = Ps[(ty << 2) + i][kk];
            float4 b4 = *reinterpret_cast<const float4*>(&Vs[kk][tx << 2]);
            float bb[4] = {b4.x, b4.y, b4.z, b4.w};
#pragma unroll
            for (int i = 0; i < 4; i++)
#pragma unroll
                for (int j = 0; j < 4; j++)
                    acc[i][j] = fmaf(a[i], bb[j], acc[i][j]);
        }
        __syncthreads();
    }
#pragma unroll
    for (int i = 0; i < 4; i++) {
        float4 o = {acc[i][0], acc[i][1], acc[i][2], acc[i][3]};
        *reinterpret_cast<float4*>(&op[(long)(q0 + (ty << 2) + i) * Cq + (tx << 2)]) = o;
    }
}

// ---------------- residual add + layernorm (in-place into x) ----------------
__device__ __forceinline__ float block_sum768(float val, float* sh)
{
#pragma unroll
    for (int o = 16; o > 0; o >>= 1) val += __shfl_xor_sync(0xffffffffu, val, o);
    __syncthreads();
    if ((threadIdx.x & 31) == 0) sh[threadIdx.x >> 5] = val;
    __syncthreads();
    float tot = 0.f;
#pragma unroll
    for (int i = 0; i < 8; i++) tot += sh[i];
    return tot;
}

__global__ void __launch_bounds__(256)
add_ln_kernel(float* __restrict__ x, const float* __restrict__ y,
              const float* __restrict__ g, const float* __restrict__ bta)
{
    __shared__ float sh[8];
    long row = blockIdx.x;
    int tid = threadIdx.x;
    float v[3];
    float s = 0.f;
#pragma unroll
    for (int j = 0; j < 3; j++) {
        int c = tid + j * 256;
        v[j] = x[row * Cq + c] + y[row * Cq + c];
        s += v[j];
    }
    float mu = block_sum768(s, sh) * (1.f / Cq);
    float s2 = 0.f;
#pragma unroll
    for (int j = 0; j < 3; j++) { float d = v[j] - mu; s2 += d * d; }
    float var = block_sum768(s2, sh) * (1.f / Cq);
    float rstd = rsqrtf(var + 1e-5f);
#pragma unroll
    for (int j = 0; j < 3; j++) {
        int c = tid + j * 256;
        x[row * Cq + c] = (v[j] - mu) * rstd * g[c] + bta[c];
    }
}

// ---------------- launch ----------------------------------------------------
extern "C" void kernel_launch(void* const* d_in, const int* in_sizes, int n_in,
                              void* d_out, int out_size)
{
    const int*   ids  = (const int*)  d_in[0];
    const float* emb  = (const float*)d_in[1];
    const float* pos  = (const float*)d_in[2];
    const float* Wq   = (const float*)d_in[3];
    const float* Wk   = (const float*)d_in[4];
    const float* Wv   = (const float*)d_in[5];
    const float* Wo   = (const float*)d_in[6];
    const float* bo   = (const float*)d_in[7];
    const float* ln1g = (const float*)d_in[8];
    const float* ln1b = (const float*)d_in[9];
    const float* W1   = (const float*)d_in[10];
    const float* b1   = (const float*)d_in[11];
    const float* W2   = (const float*)d_in[12];
    const float* b2   = (const float*)d_in[13];
    const float* ln2g = (const float*)d_in[14];
    const float* ln2b = (const float*)d_in[15];
    const float* decW = (const float*)d_in[16];
    const float* decb = (const float*)d_in[17];
    float* out = (float*)d_out;

    float *x, *q, *k, *v, *att, *mb, *rsb, *t1, *t2, *ffn;
    cudaGetSymbolAddress((void**)&x,   g_x);
    cudaGetSymbolAddress((void**)&q,   g_q);
    cudaGetSymbolAddress((void**)&k,   g_k);
    cudaGetSymbolAddress((void**)&v,   g_v);
    cudaGetSymbolAddress((void**)&att, g_att);
    cudaGetSymbolAddress((void**)&mb,  g_m);
    cudaGetSymbolAddress((void**)&rsb, g_rs);
    cudaGetSymbolAddress((void**)&t1,  g_t1);
    cudaGetSymbolAddress((void**)&t2,  g_t2);
    cudaGetSymbolAddress((void**)&ffn, g_ffn);

    embed_kernel<<<(Mq * Cq + 255) / 256, 256>>>(ids, emb, pos, x);

    for (int l = 0; l < Lq; l++) {
        const float* Wql = Wq + (size_t)l * Hq * Cq * Dq;
        const float* Wkl = Wk + (size_t)l * Hq * Cq * Dq;
        const float* Wvl = Wv + (size_t)l * Hq * Cq * Dq;
        const float* Wol = Wo + (size_t)l * Cq * Cq;
        const float* bol = bo + (size_t)l * Cq;
        const float* W1l = W1 + (size_t)l * Cq * FFq;
        const float* b1l = b1 + (size_t)l * FFq;
        const float* W2l = W2 + (size_t)l * FFq * Cq;
        const float* b2l = b2 + (size_t)l * Cq;

        // QKV: per-head GEMMs batched over z (12 heads), outputs in [BT, H*D]
        gemm_kernel<<<dim3(1, Mq / 64, Hq), 256>>>(x, Wql, nullptr, q,
            Cq, Cq, Dq, Cq, (long)Cq * Dq, Dq, 0);
        gemm_kernel<<<dim3(1, Mq / 64, Hq), 256>>>(x, Wkl, nullptr, k,
            Cq, Cq, Dq, Cq, (long)Cq * Dq, Dq, 0);
        gemm_kernel<<<dim3(1, Mq / 64, Hq), 256>>>(x, Wvl, nullptr, v,
            Cq, Cq, Dq, Cq, (long)Cq * Dq, Dq, 0);

        scores_kernel<<<dim3(8, 8, BHq), 256>>>(q, k, att);
        stats_kernel<<<BHq, 512>>>(att, mb, rsb);
        av_kernel<<<dim3(8, BHq), 256>>>(att, v, mb, rsb, t1);

        // output projection
        gemm_kernel<<<dim3(Cq / 64, Mq / 64, 1), 256>>>(t1, Wol, bol, t2,
            Cq, Cq, Cq, Cq, 0, 0, 0);
        add_ln_kernel<<<Mq, 256>>>(x, t2, ln1g + (size_t)l * Cq, ln1b + (size_t)l * Cq);

        // FFN
        gemm_kernel<<<dim3(FFq / 64, Mq / 64, 1), 256>>>(x, W1l, b1l, ffn,
            Cq, Cq, FFq, FFq, 0, 0, 1);
        gemm_kernel<<<dim3(Cq / 64, Mq / 64, 1), 256>>>(ffn, W2l, b2l, t2,
            FFq, FFq, Cq, Cq, 0, 0, 0);
        add_ln_kernel<<<Mq, 256>>>(x, t2, ln2g + (size_t)l * Cq, ln2b + (size_t)l * Cq);
    }

    // decoder: [4096,768] @ [768,32000] + bias
    gemm_kernel<<<dim3(Vq / 64, Mq / 64, 1), 256>>>(x, decW, decb, out,
        Cq, Cq, Vq, Vq, 0, 0, 0);
}

// round 3
// speedup vs baseline: 5.7313x; 5.7313x over previous
#include <cuda_runtime.h>
#include <cuda_fp16.h>
#include <cstdint>

#define Bq 8
#define Tq 512
#define Cq 768
#define Hq 12
#define Dq 64
#define Lq 12
#define Vq 32000
#define FFq 3072
#define Mq (Bq*Tq)          // 4096
#define BHq (Bq*Hq)         // 96
#define TT  (Tq*Tq)         // 262144

// ---------------- scratch (device globals) ----------------------------------
__device__ float g_x  [Mq*Cq];
__device__ float g_t2 [Mq*Cq];
__device__ float g_att[(size_t)BHq*TT];
__device__ float g_m  [BHq*Tq];
__device__ float g_rs [BHq*Tq];
__device__ float g_pm [4*BHq*Tq];
__device__ float g_ps [4*BHq*Tq];

__device__ __half g_xb  [Mq*Cq];
__device__ __half g_qb  [Mq*Cq];
__device__ __half g_kb  [Mq*Cq];
__device__ __half g_vb  [Mq*Cq];
__device__ __half g_t1b [Mq*Cq];
__device__ __half g_ffnb[(size_t)Mq*FFq];
__device__ __half g_pb  [(size_t)BHq*TT];
__device__ __half g_wqb [(size_t)Lq*Cq*Cq];
__device__ __half g_wkb [(size_t)Lq*Cq*Cq];
__device__ __half g_wvb [(size_t)Lq*Cq*Cq];
__device__ __half g_wob [(size_t)Lq*Cq*Cq];
__device__ __half g_w1b [(size_t)Lq*Cq*FFq];
__device__ __half g_w2b [(size_t)Lq*FFq*Cq];
__device__ __half g_wdb [(size_t)Cq*Vq];

// ---------------- small helpers ---------------------------------------------
__device__ __forceinline__ uint32_t s2u(const void* p) {
    return (uint32_t)__cvta_generic_to_shared(p);
}
__device__ __forceinline__ void cpa16(void* smem, const void* gmem) {
    uint32_t s = s2u(smem);
    asm volatile("cp.async.cg.shared.global [%0], [%1], 16;\n" :: "r"(s), "l"(gmem));
}
__device__ __forceinline__ void ldm_x4(uint32_t* r, uint32_t addr) {
    asm volatile("ldmatrix.sync.aligned.m8n8.x4.shared.b16 {%0,%1,%2,%3}, [%4];"
        : "=r"(r[0]), "=r"(r[1]), "=r"(r[2]), "=r"(r[3]) : "r"(addr));
}
__device__ __forceinline__ void ldm_x4_t(uint32_t* r, uint32_t addr) {
    asm volatile("ldmatrix.sync.aligned.m8n8.x4.trans.shared.b16 {%0,%1,%2,%3}, [%4];"
        : "=r"(r[0]), "=r"(r[1]), "=r"(r[2]), "=r"(r[3]) : "r"(addr));
}
__device__ __forceinline__ void mma16816(float* c, const uint32_t* a, uint32_t b0, uint32_t b1) {
    asm volatile(
        "mma.sync.aligned.m16n8k16.row.col.f32.f16.f16.f32 "
        "{%0,%1,%2,%3}, {%4,%5,%6,%7}, {%8,%9}, {%0,%1,%2,%3};"
        : "+f"(c[0]), "+f"(c[1]), "+f"(c[2]), "+f"(c[3])
        : "r"(a[0]), "r"(a[1]), "r"(a[2]), "r"(a[3]), "r"(b0), "r"(b1));
}

// ---------------- fp16 tensor-core GEMM --------------------------------------
// C[M,N] = alpha * A[M,K] * op(B) (+bias) (+relu), A/B fp16 in gmem, C fp32 or fp16.
// BT=false: B is [K,N] row-major. BT=true: B is [N,K] row-major (B^T GEMM).
// BM=128 fixed, BK=32, 256 threads, warps 4x2, warp tile 32 x BN/2.
template<int BN, bool BT>
__global__ void __launch_bounds__(256)
gemm_tc(const __half* __restrict__ A, const __half* __restrict__ B,
        const float* __restrict__ bias, void* __restrict__ Cout,
        int K, int lda, int ldb, int ldc,
        long sAo, long sAi, long sBo, long sBi, long sCo, long sCi, int zdiv,
        float alpha, int relu, int outhalf)
{
    const int zo = blockIdx.z / zdiv, zi = blockIdx.z - zo * zdiv;
    A    += zo * sAo + zi * sAi;
    B    += zo * sBo + zi * sBi;
    float* Cf  = (float*)Cout  + zo * sCo + zi * sCi;
    __half* Ch = (__half*)Cout + zo * sCo + zi * sCi;

    const int bm = blockIdx.y * 128;
    const int bn = blockIdx.x * BN;

    __shared__ __half Asm[2][128][40];
    constexpr int BROWS = BT ? BN : 32;
    constexpr int BCOLS = BT ? 40 : (BN + 8);
    __shared__ __half Bsm[2][BROWS][BCOLS];

    const int tid  = threadIdx.x;
    const int lane = tid & 31;
    const int warp = tid >> 5;
    const int wm   = warp & 3;        // 4 warps along M
    const int wn   = warp >> 2;       // 2 warps along N
    const int m_w  = wm * 32;
    const int n_w  = wn * (BN / 2);
    constexpr int NT8  = (BN / 2) / 8;
    constexpr int NT16 = (BN / 2) / 16;

    const __half* Ag = A + (long)bm * lda;
    const __half* Bg = BT ? (B + (long)bn * ldb) : (B + bn);

    float acc[2][NT8][4];
#pragma unroll
    for (int i = 0; i < 2; i++)
#pragma unroll
        for (int j = 0; j < NT8; j++)
#pragma unroll
            for (int q = 0; q < 4; q++) acc[i][j][q] = 0.f;

    auto stage = [&](int b, int k0) {
#pragma unroll
        for (int i = 0; i < 2; i++) {                      // A: 512 chunks
            int ci = tid + i * 256;
            int r = ci >> 2, kc = (ci & 3) << 3;
            cpa16(&Asm[b][r][kc], Ag + (long)r * lda + k0 + kc);
        }
        if (BT) {
            constexpr int IT = (BN * 4) / 256;
#pragma unroll
            for (int i = 0; i < IT; i++) {
                int ci = tid + i * 256;
                int r = ci >> 2, kc = (ci & 3) << 3;
                cpa16(&Bsm[b][r][kc], Bg + (long)r * ldb + k0 + kc);
            }
        } else {
            constexpr int CH = BN / 8;                     // 16B chunks per row
            constexpr int IT = (32 * CH) / 256;
#pragma unroll
            for (int i = 0; i < IT; i++) {
                int ci = tid + i * 256;
                int r = ci / CH, nc = (ci % CH) << 3;
                cpa16(&Bsm[b][r][nc], Bg + (long)(k0 + r) * ldb + nc);
            }
        }
    };

    auto compute = [&](int b) {
        uint32_t aBase = s2u(&Asm[b][0][0]);
        uint32_t bBase = s2u(&Bsm[b][0][0]);
#pragma unroll
        for (int kk = 0; kk < 32; kk += 16) {
            uint32_t ar[2][4];
#pragma unroll
            for (int mt = 0; mt < 2; mt++) {
                uint32_t addr = aBase +
                    2u * ((m_w + mt * 16 + (lane & 15)) * 40 + kk + ((lane >> 4) << 3));
                ldm_x4(ar[mt], addr);
            }
            uint32_t br[NT16][4];
#pragma unroll
            for (int nt = 0; nt < NT16; nt++) {
                if (BT) {
                    uint32_t addr = bBase +
                        2u * ((n_w + nt * 16 + (lane & 15)) * 40 + kk + ((lane >> 4) << 3));
                    ldm_x4(br[nt], addr);
                } else {
                    uint32_t addr = bBase +
                        2u * ((kk + (lane & 15)) * BCOLS + n_w + nt * 16 + ((lane >> 4) << 3));
                    ldm_x4_t(br[nt], addr);
                }
            }
#pragma unroll
            for (int mt = 0; mt < 2; mt++)
#pragma unroll
                for (int n8 = 0; n8 < NT8; n8++) {
                    int nt = n8 >> 1, h = n8 & 1;
                    uint32_t b0, b1;
                    if (BT) { b0 = br[nt][h];     b1 = br[nt][2 + h];     }
                    else    { b0 = br[nt][h * 2]; b1 = br[nt][h * 2 + 1]; }
                    mma16816(acc[mt][n8], ar[mt], b0, b1);
                }
        }
    };

    const int ntile = K >> 5;
    int buf = 0;
    stage(0, 0);
    asm volatile("cp.async.commit_group;");
    for (int kt = 0; kt < ntile; kt++) {
        asm volatile("cp.async.wait_group 0;");
        __syncthreads();
        if (kt + 1 < ntile) stage(buf ^ 1, (kt + 1) << 5);
        asm volatile("cp.async.commit_group;");
        compute(buf);
        __syncthreads();
        buf ^= 1;
    }

    // epilogue
    const int r0 = bm + m_w + (lane >> 2);
    const int c0 = bn + n_w + ((lane & 3) << 1);
#pragma unroll
    for (int n8 = 0; n8 < NT8; n8++) {
        int c = c0 + n8 * 8;
        float bb0 = 0.f, bb1 = 0.f;
        if (bias) { bb0 = __ldg(&bias[c]); bb1 = __ldg(&bias[c + 1]); }
#pragma unroll
        for (int mt = 0; mt < 2; mt++) {
#pragma unroll
            for (int hh = 0; hh < 2; hh++) {
                int r = r0 + mt * 16 + hh * 8;
                float v0 = acc[mt][n8][hh * 2 + 0] * alpha + bb0;
                float v1 = acc[mt][n8][hh * 2 + 1] * alpha + bb1;
                if (relu) { v0 = fmaxf(v0, 0.f); v1 = fmaxf(v1, 0.f); }
                if (outhalf) {
                    *reinterpret_cast<__half2*>(Ch + (long)r * ldc + c) =
                        __floats2half2_rn(v0, v1);
                } else {
                    *reinterpret_cast<float2*>(Cf + (long)r * ldc + c) = make_float2(v0, v1);
                }
            }
        }
    }
}

// ---------------- conversions ------------------------------------------------
__global__ void f2h_kernel(const float* __restrict__ in, __half* __restrict__ out, long n)
{
    long i = (long)blockIdx.x * blockDim.x + threadIdx.x;
    if (i * 4 >= n) return;
    float4 v = reinterpret_cast<const float4*>(in)[i];
    reinterpret_cast<__half2*>(out)[i * 2 + 0] = __floats2half2_rn(v.x, v.y);
    reinterpret_cast<__half2*>(out)[i * 2 + 1] = __floats2half2_rn(v.z, v.w);
}

// W[l][h][c][d] -> Wt[l][c][h*64+d]  (fp16)
__global__ void qkv_tr_kernel(const float* __restrict__ W, __half* __restrict__ Wt)
{
    long i = (long)blockIdx.x * blockDim.x + threadIdx.x;   // over L*H*C*D / 4
    long idx = i * 4;
    if (idx >= (long)Lq * Hq * Cq * Dq) return;
    int d = idx & 63;
    long rest = idx >> 6;
    int c = rest % Cq;
    rest /= Cq;
    int h = rest % Hq;
    int l = rest / Hq;
    float4 v = *reinterpret_cast<const float4*>(&W[idx]);
    __half* o = &Wt[((long)l * Cq + c) * Cq + h * Dq + d];
    reinterpret_cast<__half2*>(o)[0] = __floats2half2_rn(v.x, v.y);
    reinterpret_cast<__half2*>(o)[1] = __floats2half2_rn(v.z, v.w);
}

// ---------------- embed -------------------------------------------------------
__global__ void embed_kernel(const int* __restrict__ ids, const float* __restrict__ emb,
                             const float* __restrict__ pos,
                             float* __restrict__ x, __half* __restrict__ xb)
{
    int idx = blockIdx.x * blockDim.x + threadIdx.x;
    if (idx >= Mq * Cq) return;
    int m = idx / Cq, c = idx - m * Cq;
    int t = m & (Tq - 1);
    int tok = ids[m];
    float v = emb[(size_t)tok * Cq + c] + pos[(size_t)t * Cq + c];
    x[idx]  = v;
    xb[idx] = __float2half(v);
}

// ---------------- column softmax stats (softmax over q axis) -----------------
__global__ void __launch_bounds__(512)
stats1_kernel(const float* __restrict__ att, float* __restrict__ pm, float* __restrict__ ps)
{
    int bh = blockIdx.x;
    int q0 = blockIdx.y * 128;
    int k  = threadIdx.x;
    const float* ap = att + (long)bh * TT + (long)q0 * Tq;
    float m0 = -1e30f, s0 = 0.f, m1 = -1e30f, s1 = 0.f;
    for (int q = 0; q < 128; q += 2) {
        float v0 = ap[(long)q * Tq + k];
        float v1 = ap[(long)(q + 1) * Tq + k];
        float nm0 = fmaxf(m0, v0);
        s0 = s0 * __expf(m0 - nm0) + __expf(v0 - nm0); m0 = nm0;
        float nm1 = fmaxf(m1, v1);
        s1 = s1 * __expf(m1 - nm1) + __expf(v1 - nm1); m1 = nm1;
    }
    float m = fmaxf(m0, m1);
    float s = s0 * __expf(m0 - m) + s1 * __expf(m1 - m);
    long o = ((long)blockIdx.y * BHq + bh) * Tq + k;
    pm[o] = m; ps[o] = s;
}

__global__ void __launch_bounds__(512)
stats2_kernel(const float* __restrict__ pm, const float* __restrict__ ps,
              float* __restrict__ mb, float* __restrict__ rsb)
{
    int i = blockIdx.x * 512 + threadIdx.x;     // bh*Tq + k
    float m = -1e30f;
#pragma unroll
    for (int p = 0; p < 4; p++) m = fmaxf(m, pm[p * BHq * Tq + i]);
    float s = 0.f;
#pragma unroll
    for (int p = 0; p < 4; p++) s += ps[p * BHq * Tq + i] * __expf(pm[p * BHq * Tq + i] - m);
    mb[i]  = m;
    rsb[i] = 1.f / s;
}

// Pb = fp16(exp(att - m[k]) * rs[k])
__global__ void pexp_kernel(const float* __restrict__ att, const float* __restrict__ mb,
                            const float* __restrict__ rsb, __half* __restrict__ pb)
{
    long i = (long)blockIdx.x * blockDim.x + threadIdx.x;   // group of 4
    long base = i * 4;
    if (base >= (long)BHq * TT) return;
    int k  = (int)(base & (Tq - 1));
    int bh = (int)(base >> 18);                // /(512*512)
    float4 a = reinterpret_cast<const float4*>(att)[i];
    const float* mp = mb  + (long)bh * Tq + k;
    const float* rp = rsb + (long)bh * Tq + k;
    float e0 = __expf(a.x - mp[0]) * rp[0];
    float e1 = __expf(a.y - mp[1]) * rp[1];
    float e2 = __expf(a.z - mp[2]) * rp[2];
    float e3 = __expf(a.w - mp[3]) * rp[3];
    reinterpret_cast<__half2*>(pb)[i * 2 + 0] = __floats2half2_rn(e0, e1);
    reinterpret_cast<__half2*>(pb)[i * 2 + 1] = __floats2half2_rn(e2, e3);
}

// ---------------- residual add + layernorm ------------------------------------
__device__ __forceinline__ float block_sum768(float val, float* sh)
{
#pragma unroll
    for (int o = 16; o > 0; o >>= 1) val += __shfl_xor_sync(0xffffffffu, val, o);
    __syncthreads();
    if ((threadIdx.x & 31) == 0) sh[threadIdx.x >> 5] = val;
    __syncthreads();
    float tot = 0.f;
#pragma unroll
    for (int i = 0; i < 8; i++) tot += sh[i];
    return tot;
}

__global__ void __launch_bounds__(256)
add_ln_kernel(float* __restrict__ x, const float* __restrict__ y,
              const float* __restrict__ g, const float* __restrict__ bta,
              __half* __restrict__ xb)
{
    __shared__ float sh[8];
    long row = blockIdx.x;
    int tid = threadIdx.x;
    float v[3];
    float s = 0.f;
#pragma unroll
    for (int j = 0; j < 3; j++) {
        int c = tid + j * 256;
        v[j] = x[row * Cq + c] + y[row * Cq + c];
        s += v[j];
    }
    float mu = block_sum768(s, sh) * (1.f / Cq);
    float s2 = 0.f;
#pragma unroll
    for (int j = 0; j < 3; j++) { float d = v[j] - mu; s2 += d * d; }
    float var = block_sum768(s2, sh) * (1.f / Cq);
    float rstd = rsqrtf(var + 1e-5f);
#pragma unroll
    for (int j = 0; j < 3; j++) {
        int c = tid + j * 256;
        float o = (v[j] - mu) * rstd * g[c] + bta[c];
        x[row * Cq + c]  = o;
        xb[row * Cq + c] = __float2half(o);
    }
}

// ---------------- launch -------------------------------------------------------
extern "C" void kernel_launch(void* const* d_in, const int* in_sizes, int n_in,
                              void* d_out, int out_size)
{
    const int*   ids  = (const int*)  d_in[0];
    const float* emb  = (const float*)d_in[1];
    const float* pos  = (const float*)d_in[2];
    const float* Wq   = (const float*)d_in[3];
    const float* Wk   = (const float*)d_in[4];
    const float* Wv   = (const float*)d_in[5];
    const float* Wo   = (const float*)d_in[6];
    const float* bo   = (const float*)d_in[7];
    const float* ln1g = (const float*)d_in[8];
    const float* ln1b = (const float*)d_in[9];
    const float* W1   = (const float*)d_in[10];
    const float* b1   = (const float*)d_in[11];
    const float* W2   = (const float*)d_in[12];
    const float* b2   = (const float*)d_in[13];
    const float* ln2g = (const float*)d_in[14];
    const float* ln2b = (const float*)d_in[15];
    const float* decW = (const float*)d_in[16];
    const float* decb = (const float*)d_in[17];
    float* out = (float*)d_out;

    float *x, *t2, *att, *mb, *rsb, *pm, *ps;
    __half *xb, *qb, *kb, *vb, *t1b, *ffnb, *pb;
    __half *wqb, *wkb, *wvb, *wob, *w1b, *w2b, *wdb;
    cudaGetSymbolAddress((void**)&x,    g_x);
    cudaGetSymbolAddress((void**)&t2,   g_t2);
    cudaGetSymbolAddress((void**)&att,  g_att);
    cudaGetSymbolAddress((void**)&mb,   g_m);
    cudaGetSymbolAddress((void**)&rsb,  g_rs);
    cudaGetSymbolAddress((void**)&pm,   g_pm);
    cudaGetSymbolAddress((void**)&ps,   g_ps);
    cudaGetSymbolAddress((void**)&xb,   g_xb);
    cudaGetSymbolAddress((void**)&qb,   g_qb);
    cudaGetSymbolAddress((void**)&kb,   g_kb);
    cudaGetSymbolAddress((void**)&vb,   g_vb);
    cudaGetSymbolAddress((void**)&t1b,  g_t1b);
    cudaGetSymbolAddress((void**)&ffnb, g_ffnb);
    cudaGetSymbolAddress((void**)&pb,   g_pb);
    cudaGetSymbolAddress((void**)&wqb,  g_wqb);
    cudaGetSymbolAddress((void**)&wkb,  g_wkb);
    cudaGetSymbolAddress((void**)&wvb,  g_wvb);
    cudaGetSymbolAddress((void**)&wob,  g_wob);
    cudaGetSymbolAddress((void**)&w1b,  g_w1b);
    cudaGetSymbolAddress((void**)&w2b,  g_w2b);
    cudaGetSymbolAddress((void**)&wdb,  g_wdb);

    // weight conversions (fp16)
    {
        long n = (long)Lq * Cq * Cq;
        int  bl = 256;
        long g4 = (n / 4 + bl - 1) / bl;
        qkv_tr_kernel<<<(unsigned)g4, bl>>>(Wq, wqb);
        qkv_tr_kernel<<<(unsigned)g4, bl>>>(Wk, wkb);
        qkv_tr_kernel<<<(unsigned)g4, bl>>>(Wv, wvb);
        f2h_kernel<<<(unsigned)g4, bl>>>(Wo, wob, n);
        long n1 = (long)Lq * Cq * FFq;
        f2h_kernel<<<(unsigned)((n1 / 4 + bl - 1) / bl), bl>>>(W1, w1b, n1);
        f2h_kernel<<<(unsigned)((n1 / 4 + bl - 1) / bl), bl>>>(W2, w2b, n1);
        long nd = (long)Cq * Vq;
        f2h_kernel<<<(unsigned)((nd / 4 + bl - 1) / bl), bl>>>(decW, wdb, nd);
    }

    embed_kernel<<<(Mq * Cq + 255) / 256, 256>>>(ids, emb, pos, x, xb);

    for (int l = 0; l < Lq; l++) {
        const __half* wql = wqb + (size_t)l * Cq * Cq;
        const __half* wkl = wkb + (size_t)l * Cq * Cq;
        const __half* wvl = wvb + (size_t)l * Cq * Cq;
        const __half* wol = wob + (size_t)l * Cq * Cq;
        const __half* w1l = w1b + (size_t)l * Cq * FFq;
        const __half* w2l = w2b + (size_t)l * FFq * Cq;
        const float* bol = bo + (size_t)l * Cq;
        const float* b1l = b1 + (size_t)l * FFq;
        const float* b2l = b2 + (size_t)l * Cq;

        // QKV (out fp16)
        gemm_tc<128, false><<<dim3(Cq / 128, Mq / 128, 1), 256>>>(
            xb, wql, nullptr, qb, Cq, Cq, Cq, Cq, 0, 0, 0, 0, 0, 0, 1, 1.f, 0, 1);
        gemm_tc<128, false><<<dim3(Cq / 128, Mq / 128, 1), 256>>>(
            xb, wkl, nullptr, kb, Cq, Cq, Cq, Cq, 0, 0, 0, 0, 0, 0, 1, 1.f, 0, 1);
        gemm_tc<128, false><<<dim3(Cq / 128, Mq / 128, 1), 256>>>(
            xb, wvl, nullptr, vb, Cq, Cq, Cq, Cq, 0, 0, 0, 0, 0, 0, 1, 1.f, 0, 1);

        // scores: att[bh][q][k] = 0.125 * Q K^T   (NT, out fp32)
        gemm_tc<128, true><<<dim3(Tq / 128, Tq / 128, BHq), 256>>>(
            qb, kb, nullptr, att, Dq, Cq, Cq, Tq,
            (long)Tq * Cq, Dq, (long)Tq * Cq, Dq, (long)Hq * TT, TT, Hq,
            0.125f, 0, 0);

        stats1_kernel<<<dim3(BHq, 4), 512>>>(att, pm, ps);
        stats2_kernel<<<BHq * Tq / 512, 512>>>(pm, ps, mb, rsb);
        pexp_kernel<<<(unsigned)(((long)BHq * TT / 4 + 255) / 256), 256>>>(att, mb, rsb, pb);

        // AV: t1b[b][q][h*64+d] (out fp16)
        gemm_tc<64, false><<<dim3(1, Tq / 128, BHq), 256>>>(
            pb, vb, nullptr, t1b, Tq, Tq, Cq, Cq,
            (long)Hq * TT, TT, (long)Tq * Cq, Dq, (long)Tq * Cq, Dq, Hq,
            1.f, 0, 1);

        // output projection (out fp32) + add/LN
        gemm_tc<128, false><<<dim3(Cq / 128, Mq / 128, 1), 256>>>(
            t1b, wol, bol, t2, Cq, Cq, Cq, Cq, 0, 0, 0, 0, 0, 0, 1, 1.f, 0, 0);
        add_ln_kernel<<<Mq, 256>>>(x, t2, ln1g + (size_t)l * Cq, ln1b + (size_t)l * Cq, xb);

        // FFN
        gemm_tc<128, false><<<dim3(FFq / 128, Mq / 128, 1), 256>>>(
            xb, w1l, b1l, ffnb, Cq, Cq, FFq, FFq, 0, 0, 0, 0, 0, 0, 1, 1.f, 1, 1);
        gemm_tc<128, false><<<dim3(Cq / 128, Mq / 128, 1), 256>>>(
            ffnb, w2l, b2l, t2, FFq, FFq, Cq, Cq, 0, 0, 0, 0, 0, 0, 1, 1.f, 0, 0);
        add_ln_kernel<<<Mq, 256>>>(x, t2, ln2g + (size_t)l * Cq, ln2b + (size_t)l * Cq, xb);
    }

    // decoder
    gemm_tc<128, false><<<dim3(Vq / 128, Mq / 128, 1), 256>>>(
        xb, wdb, decb, out, Cq, Cq, Vq, Vq, 0, 0, 0, 0, 0, 0, 1, 1.f, 0, 0);
}

// round 4
// speedup vs baseline: 6.6078x; 1.1529x over previous
#include <cuda_runtime.h>
#include <cuda_fp16.h>
#include <cstdint>

#define Bq 8
#define Tq 512
#define Cq 768
#define Hq 12
#define Dq 64
#define Lq 12
#define Vq 32000
#define FFq 3072
#define Mq (Bq*Tq)          // 4096
#define BHq (Bq*Hq)         // 96
#define TT  (Tq*Tq)         // 262144
#define C3  (3*Cq)          // 2304

// ---------------- scratch (device globals) ----------------------------------
__device__ float g_x  [Mq*Cq];
__device__ float g_t2 [Mq*Cq];
__device__ float g_ps [4*BHq*Tq];
__device__ float g_rs [BHq*Tq];

__device__ __half g_xb   [Mq*Cq];
__device__ __half g_qkvb [(size_t)Mq*C3];
__device__ __half g_atth [(size_t)BHq*TT];
__device__ __half g_pb   [(size_t)BHq*TT];
__device__ __half g_vs   [Mq*Cq];
__device__ __half g_t1b  [Mq*Cq];
__device__ __half g_ffnb [(size_t)Mq*FFq];
__device__ __half g_wqkv [(size_t)Lq*Cq*C3];
__device__ __half g_wob  [(size_t)Lq*Cq*Cq];
__device__ __half g_w1b  [(size_t)Lq*Cq*FFq];
__device__ __half g_w2b  [(size_t)Lq*FFq*Cq];
__device__ __half g_wdb  [(size_t)Cq*Vq];

// ---------------- small helpers ---------------------------------------------
__device__ __forceinline__ uint32_t s2u(const void* p) {
    return (uint32_t)__cvta_generic_to_shared(p);
}
__device__ __forceinline__ void cpa16(void* smem, const void* gmem) {
    uint32_t s = s2u(smem);
    asm volatile("cp.async.cg.shared.global [%0], [%1], 16;\n" :: "r"(s), "l"(gmem));
}
__device__ __forceinline__ void ldm_x4(uint32_t* r, uint32_t addr) {
    asm volatile("ldmatrix.sync.aligned.m8n8.x4.shared.b16 {%0,%1,%2,%3}, [%4];"
        : "=r"(r[0]), "=r"(r[1]), "=r"(r[2]), "=r"(r[3]) : "r"(addr));
}
__device__ __forceinline__ void ldm_x4_t(uint32_t* r, uint32_t addr) {
    asm volatile("ldmatrix.sync.aligned.m8n8.x4.trans.shared.b16 {%0,%1,%2,%3}, [%4];"
        : "=r"(r[0]), "=r"(r[1]), "=r"(r[2]), "=r"(r[3]) : "r"(addr));
}
__device__ __forceinline__ void mma16816(float* c, const uint32_t* a, uint32_t b0, uint32_t b1) {
    asm volatile(
        "mma.sync.aligned.m16n8k16.row.col.f32.f16.f16.f32 "
        "{%0,%1,%2,%3}, {%4,%5,%6,%7}, {%8,%9}, {%0,%1,%2,%3};"
        : "+f"(c[0]), "+f"(c[1]), "+f"(c[2]), "+f"(c[3])
        : "r"(a[0]), "r"(a[1]), "r"(a[2]), "r"(a[3]), "r"(b0), "r"(b1));
}

// ---------------- fp16 tensor-core GEMM (3-stage cp.async pipeline) ----------
// C[M,N] = alpha * A[M,K] * op(B) (+bias) (+relu). A/B fp16, C fp32 or fp16.
// BT=false: B is [K,N] row-major. BT=true: B is [N,K] row-major.
// BM=128, BK=32, 256 threads, warps 4x2, warp tile 32 x BN/2. Dynamic smem.
template<int BN, bool BT>
__global__ void __launch_bounds__(256)
gemm_tc(const __half* __restrict__ A, const __half* __restrict__ B,
        const float* __restrict__ bias, void* __restrict__ Cout,
        int K, int lda, int ldb, int ldc,
        long sAo, long sAi, long sBo, long sBi, long sCo, long sCi, int zdiv,
        float alpha, int relu, int outhalf)
{
    extern __shared__ __half smem_dyn[];
    constexpr int ASIZE = 128 * 40;
    constexpr int BROWS = BT ? BN : 32;
    constexpr int BCOLS = BT ? 40 : (BN + 8);
    constexpr int BSIZE = BROWS * BCOLS;
    __half* Asm = smem_dyn;                 // [3][128][40]
    __half* Bsm = smem_dyn + 3 * ASIZE;     // [3][BROWS][BCOLS]

    const int zo = blockIdx.z / zdiv, zi = blockIdx.z - zo * zdiv;
    A += zo * sAo + zi * sAi;
    B += zo * sBo + zi * sBi;
    float* Cf  = (float*)Cout  + zo * sCo + zi * sCi;
    __half* Ch = (__half*)Cout + zo * sCo + zi * sCi;

    const int bm = blockIdx.y * 128;
    const int bn = blockIdx.x * BN;

    const int tid  = threadIdx.x;
    const int lane = tid & 31;
    const int warp = tid >> 5;
    const int wm   = warp & 3;
    const int wn   = warp >> 2;
    const int m_w  = wm * 32;
    const int n_w  = wn * (BN / 2);
    constexpr int NT8  = (BN / 2) / 8;
    constexpr int NT16 = (BN / 2) / 16;

    const __half* Ag = A + (long)bm * lda;
    const __half* Bg = BT ? (B + (long)bn * ldb) : (B + bn);

    float acc[2][NT8][4];
#pragma unroll
    for (int i = 0; i < 2; i++)
#pragma unroll
        for (int j = 0; j < NT8; j++)
#pragma unroll
            for (int q = 0; q < 4; q++) acc[i][j][q] = 0.f;

    auto stage = [&](int s, int k0) {
        __half* As = Asm + s * ASIZE;
        __half* Bs = Bsm + s * BSIZE;
#pragma unroll
        for (int i = 0; i < 2; i++) {
            int ci = tid + i * 256;
            int r = ci >> 2, kc = (ci & 3) << 3;
            cpa16(&As[r * 40 + kc], Ag + (long)r * lda + k0 + kc);
        }
        if (BT) {
            constexpr int IT = (BN * 4) / 256;
#pragma unroll
            for (int i = 0; i < IT; i++) {
                int ci = tid + i * 256;
                int r = ci >> 2, kc = (ci & 3) << 3;
                cpa16(&Bs[r * 40 + kc], Bg + (long)r * ldb + k0 + kc);
            }
        } else {
            constexpr int CH = BN / 8;
            constexpr int IT = (32 * CH) / 256;
#pragma unroll
            for (int i = 0; i < IT; i++) {
                int ci = tid + i * 256;
                int r = ci / CH, nc = (ci % CH) << 3;
                cpa16(&Bs[r * BCOLS + nc], Bg + (long)(k0 + r) * ldb + nc);
            }
        }
    };

    auto compute = [&](int s) {
        uint32_t aBase = s2u(Asm + s * ASIZE);
        uint32_t bBase = s2u(Bsm + s * BSIZE);
#pragma unroll
        for (int kk = 0; kk < 32; kk += 16) {
            uint32_t ar[2][4];
#pragma unroll
            for (int mt = 0; mt < 2; mt++) {
                uint32_t addr = aBase +
                    2u * ((m_w + mt * 16 + (lane & 15)) * 40 + kk + ((lane >> 4) << 3));
                ldm_x4(ar[mt], addr);
            }
            uint32_t br[NT16][4];
#pragma unroll
            for (int nt = 0; nt < NT16; nt++) {
                if (BT) {
                    uint32_t addr = bBase +
                        2u * ((n_w + nt * 16 + (lane & 15)) * 40 + kk + ((lane >> 4) << 3));
                    ldm_x4(br[nt], addr);
                } else {
                    uint32_t addr = bBase +
                        2u * ((kk + (lane & 15)) * BCOLS + n_w + nt * 16 + ((lane >> 4) << 3));
                    ldm_x4_t(br[nt], addr);
                }
            }
#pragma unroll
            for (int mt = 0; mt < 2; mt++)
#pragma unroll
                for (int n8 = 0; n8 < NT8; n8++) {
                    int nt = n8 >> 1, h = n8 & 1;
                    uint32_t b0, b1;
                    if (BT) { b0 = br[nt][h];     b1 = br[nt][2 + h];     }
                    else    { b0 = br[nt][h * 2]; b1 = br[nt][h * 2 + 1]; }
                    mma16816(acc[mt][n8], ar[mt], b0, b1);
                }
        }
    };

    const int ntile = K >> 5;                 // all K here are multiples of 64
    stage(0, 0);
    asm volatile("cp.async.commit_group;");
    stage(1, 32);
    asm volatile("cp.async.commit_group;");
    for (int kt = 0; kt < ntile; kt++) {
        asm volatile("cp.async.wait_group 1;");
        __syncthreads();
        if (kt + 2 < ntile) stage((kt + 2) % 3, (kt + 2) << 5);
        asm volatile("cp.async.commit_group;");
        compute(kt % 3);
    }

    // epilogue
    const int r0 = bm + m_w + (lane >> 2);
    const int c0 = bn + n_w + ((lane & 3) << 1);
#pragma unroll
    for (int n8 = 0; n8 < NT8; n8++) {
        int c = c0 + n8 * 8;
        float bb0 = 0.f, bb1 = 0.f;
        if (bias) { bb0 = __ldg(&bias[c]); bb1 = __ldg(&bias[c + 1]); }
#pragma unroll
        for (int mt = 0; mt < 2; mt++) {
#pragma unroll
            for (int hh = 0; hh < 2; hh++) {
                int r = r0 + mt * 16 + hh * 8;
                float v0 = acc[mt][n8][hh * 2 + 0] * alpha + bb0;
                float v1 = acc[mt][n8][hh * 2 + 1] * alpha + bb1;
                if (relu) { v0 = fmaxf(v0, 0.f); v1 = fmaxf(v1, 0.f); }
                if (outhalf) {
                    *reinterpret_cast<__half2*>(Ch + (long)r * ldc + c) =
                        __floats2half2_rn(v0, v1);
                } else {
                    *reinterpret_cast<float2*>(Cf + (long)r * ldc + c) = make_float2(v0, v1);
                }
            }
        }
    }
}

// smem sizes (bytes) for the three instantiations
#define SMEM_128F (3*(128*40 + 32*136)*2)   // 56832
#define SMEM_128T (3*(128*40 + 128*40)*2)   // 61440
#define SMEM_64F  (3*(128*40 + 32*72)*2)    // 44544

// ---------------- conversions ------------------------------------------------
__global__ void f2h_kernel(const float* __restrict__ in, __half* __restrict__ out, long n)
{
    long i = (long)blockIdx.x * blockDim.x + threadIdx.x;
    if (i * 4 >= n) return;
    float4 v = reinterpret_cast<const float4*>(in)[i];
    reinterpret_cast<__half2*>(out)[i * 2 + 0] = __floats2half2_rn(v.x, v.y);
    reinterpret_cast<__half2*>(out)[i * 2 + 1] = __floats2half2_rn(v.z, v.w);
}

// W[l][h][c][d] -> Wt[l][c][coloff + h*64 + d]  (fp16, ld = 2304)
__global__ void qkv_tr_kernel(const float* __restrict__ W, __half* __restrict__ Wt, int coloff)
{
    long i = (long)blockIdx.x * blockDim.x + threadIdx.x;
    long idx = i * 4;
    if (idx >= (long)Lq * Hq * Cq * Dq) return;
    int d = idx & 63;
    long rest = idx >> 6;
    int c = rest % Cq;
    rest /= Cq;
    int h = rest % Hq;
    int l = rest / Hq;
    float4 v = *reinterpret_cast<const float4*>(&W[idx]);
    __half* o = &Wt[((long)l * Cq + c) * C3 + coloff + h * Dq + d];
    reinterpret_cast<__half2*>(o)[0] = __floats2half2_rn(v.x, v.y);
    reinterpret_cast<__half2*>(o)[1] = __floats2half2_rn(v.z, v.w);
}

// ---------------- embed -------------------------------------------------------
__global__ void embed_kernel(const int* __restrict__ ids, const float* __restrict__ emb,
                             const float* __restrict__ pos,
                             float* __restrict__ x, __half* __restrict__ xb)
{
    int idx = blockIdx.x * blockDim.x + threadIdx.x;
    if (idx >= Mq * Cq) return;
    int m = idx / Cq, c = idx - m * Cq;
    int t = m & (Tq - 1);
    int tok = ids[m];
    float v = emb[(size_t)tok * Cq + c] + pos[(size_t)t * Cq + c];
    x[idx]  = v;
    xb[idx] = __float2half(v);
}

// ---------------- softmax over q: e = exp(att-4); column partial sums --------
__global__ void __launch_bounds__(512)
sumexp_kernel(const __half* __restrict__ att, __half* __restrict__ pb,
              float* __restrict__ ps)
{
    int bh = blockIdx.x;
    int qc = blockIdx.y;
    int k  = threadIdx.x;
    const __half* ap = att + (long)bh * TT + (long)qc * 128 * Tq;
    __half*       pp = pb  + (long)bh * TT + (long)qc * 128 * Tq;
    float s = 0.f;
#pragma unroll 4
    for (int q = 0; q < 128; q++) {
        float v = __half2float(ap[(long)q * Tq + k]);
        __half h = __float2half(__expf(v - 4.f));
        pp[(long)q * Tq + k] = h;
        s += __half2float(h);
    }
    ps[((long)qc * BHq + bh) * Tq + k] = s;
}

__global__ void __launch_bounds__(512)
rs_kernel(const float* __restrict__ ps, float* __restrict__ rs)
{
    int i = blockIdx.x * 512 + threadIdx.x;          // bh*Tq + k
    float s = ps[i] + ps[BHq * Tq + i] + ps[2 * BHq * Tq + i] + ps[3 * BHq * Tq + i];
    rs[i] = 1.f / s;
}

// vs[m][c] = rs[(b,h),t] * V[m][c]  (V = qkv cols 1536..2303)
__global__ void vscale_kernel(const __half* __restrict__ qkv,
                              const float* __restrict__ rs, __half* __restrict__ vs)
{
    int idx = blockIdx.x * blockDim.x + threadIdx.x;  // half2 units
    if (idx >= Mq * Cq / 2) return;
    int c2 = idx % (Cq / 2);
    int m  = idx / (Cq / 2);
    int c  = c2 * 2;
    int b  = m >> 9, t = m & 511, h = c >> 6;
    float r = rs[(((long)b * Hq + h) << 9) + t];
    __half2 v = *reinterpret_cast<const __half2*>(&qkv[(long)m * C3 + 1536 + c]);
    float2 f = __half22float2(v);
    *reinterpret_cast<__half2*>(&vs[(long)m * Cq + c]) = __floats2half2_rn(f.x * r, f.y * r);
}

// ---------------- residual add + layernorm ------------------------------------
__device__ __forceinline__ float block_sum768(float val, float* sh)
{
#pragma unroll
    for (int o = 16; o > 0; o >>= 1) val += __shfl_xor_sync(0xffffffffu, val, o);
    __syncthreads();
    if ((threadIdx.x & 31) == 0) sh[threadIdx.x >> 5] = val;
    __syncthreads();
    float tot = 0.f;
#pragma unroll
    for (int i = 0; i < 8; i++) tot += sh[i];
    return tot;
}

__global__ void __launch_bounds__(256)
add_ln_kernel(float* __restrict__ x, const float* __restrict__ y,
              const float* __restrict__ g, const float* __restrict__ bta,
              __half* __restrict__ xb)
{
    __shared__ float sh[8];
    long row = blockIdx.x;
    int tid = threadIdx.x;
    float v[3];
    float s = 0.f;
#pragma unroll
    for (int j = 0; j < 3; j++) {
        int c = tid + j * 256;
        v[j] = x[row * Cq + c] + y[row * Cq + c];
        s += v[j];
    }
    float mu = block_sum768(s, sh) * (1.f / Cq);
    float s2 = 0.f;
#pragma unroll
    for (int j = 0; j < 3; j++) { float d = v[j] - mu; s2 += d * d; }
    float var = block_sum768(s2, sh) * (1.f / Cq);
    float rstd = rsqrtf(var + 1e-5f);
#pragma unroll
    for (int j = 0; j < 3; j++) {
        int c = tid + j * 256;
        float o = (v[j] - mu) * rstd * g[c] + bta[c];
        x[row * Cq + c]  = o;
        xb[row * Cq + c] = __float2half(o);
    }
}

// ---------------- launch -------------------------------------------------------
extern "C" void kernel_launch(void* const* d_in, const int* in_sizes, int n_in,
                              void* d_out, int out_size)
{
    const int*   ids  = (const int*)  d_in[0];
    const float* emb  = (const float*)d_in[1];
    const float* pos  = (const float*)d_in[2];
    const float* Wq   = (const float*)d_in[3];
    const float* Wk   = (const float*)d_in[4];
    const float* Wv   = (const float*)d_in[5];
    const float* Wo   = (const float*)d_in[6];
    const float* bo   = (const float*)d_in[7];
    const float* ln1g = (const float*)d_in[8];
    const float* ln1b = (const float*)d_in[9];
    const float* W1   = (const float*)d_in[10];
    const float* b1   = (const float*)d_in[11];
    const float* W2   = (const float*)d_in[12];
    const float* b2   = (const float*)d_in[13];
    const float* ln2g = (const float*)d_in[14];
    const float* ln2b = (const float*)d_in[15];
    const float* decW = (const float*)d_in[16];
    const float* decb = (const float*)d_in[17];
    float* out = (float*)d_out;

    cudaFuncSetAttribute(gemm_tc<128, false>,
        cudaFuncAttributeMaxDynamicSharedMemorySize, SMEM_128F);
    cudaFuncSetAttribute(gemm_tc<128, true>,
        cudaFuncAttributeMaxDynamicSharedMemorySize, SMEM_128T);
    cudaFuncSetAttribute(gemm_tc<64, false>,
        cudaFuncAttributeMaxDynamicSharedMemorySize, SMEM_64F);

    float *x, *t2, *ps, *rs;
    __half *xb, *qkvb, *atth, *pb, *vs, *t1b, *ffnb;
    __half *wqkv, *wob, *w1b, *w2b, *wdb;
    cudaGetSymbolAddress((void**)&x,    g_x);
    cudaGetSymbolAddress((void**)&t2,   g_t2);
    cudaGetSymbolAddress((void**)&ps,   g_ps);
    cudaGetSymbolAddress((void**)&rs,   g_rs);
    cudaGetSymbolAddress((void**)&xb,   g_xb);
    cudaGetSymbolAddress((void**)&qkvb, g_qkvb);
    cudaGetSymbolAddress((void**)&atth, g_atth);
    cudaGetSymbolAddress((void**)&pb,   g_pb);
    cudaGetSymbolAddress((void**)&vs,   g_vs);
    cudaGetSymbolAddress((void**)&t1b,  g_t1b);
    cudaGetSymbolAddress((void**)&ffnb, g_ffnb);
    cudaGetSymbolAddress((void**)&wqkv, g_wqkv);
    cudaGetSymbolAddress((void**)&wob,  g_wob);
    cudaGetSymbolAddress((void**)&w1b,  g_w1b);
    cudaGetSymbolAddress((void**)&w2b,  g_w2b);
    cudaGetSymbolAddress((void**)&wdb,  g_wdb);

    // weight conversions
    {
        long n = (long)Lq * Cq * Cq;
        int  bl = 256;
        long g4 = (n / 4 + bl - 1) / bl;
        qkv_tr_kernel<<<(unsigned)g4, bl>>>(Wq, wqkv, 0);
        qkv_tr_kernel<<<(unsigned)g4, bl>>>(Wk, wqkv, 768);
        qkv_tr_kernel<<<(unsigned)g4, bl>>>(Wv, wqkv, 1536);
        f2h_kernel<<<(unsigned)g4, bl>>>(Wo, wob, n);
        long n1 = (long)Lq * Cq * FFq;
        f2h_kernel<<<(unsigned)((n1 / 4 + bl - 1) / bl), bl>>>(W1, w1b, n1);
        f2h_kernel<<<(unsigned)((n1 / 4 + bl - 1) / bl), bl>>>(W2, w2b, n1);
        long nd = (long)Cq * Vq;
        f2h_kernel<<<(unsigned)((nd / 4 + bl - 1) / bl), bl>>>(decW, wdb, nd);
    }

    embed_kernel<<<(Mq * Cq + 255) / 256, 256>>>(ids, emb, pos, x, xb);

    for (int l = 0; l < Lq; l++) {
        const __half* wqkvl = wqkv + (size_t)l * Cq * C3;
        const __half* wol   = wob  + (size_t)l * Cq * Cq;
        const __half* w1l   = w1b  + (size_t)l * Cq * FFq;
        const __half* w2l   = w2b  + (size_t)l * FFq * Cq;
        const float* bol = bo + (size_t)l * Cq;
        const float* b1l = b1 + (size_t)l * FFq;
        const float* b2l = b2 + (size_t)l * Cq;

        // fused QKV: [4096,768] @ [768,2304] -> qkvb fp16
        gemm_tc<128, false><<<dim3(C3 / 128, Mq / 128, 1), 256, SMEM_128F>>>(
            xb, wqkvl, nullptr, qkvb, Cq, Cq, C3, C3, 0, 0, 0, 0, 0, 0, 1, 1.f, 0, 1);

        // scores: att[bh][q][k] = 0.125 * Q K^T   (NT, out fp16)
        gemm_tc<128, true><<<dim3(Tq / 128, Tq / 128, BHq), 256, SMEM_128T>>>(
            qkvb, qkvb + 768, nullptr, atth, Dq, C3, C3, Tq,
            (long)Tq * C3, Dq, (long)Tq * C3, Dq, (long)Hq * TT, TT, Hq,
            0.125f, 0, 1);

        // softmax over q (fixed-offset exp): pb = exp(att-4), rs = 1/colsum
        sumexp_kernel<<<dim3(BHq, 4), 512>>>(atth, pb, ps);
        rs_kernel<<<BHq * Tq / 512, 512>>>(ps, rs);
        vscale_kernel<<<(Mq * Cq / 2 + 255) / 256, 256>>>(qkvb, rs, vs);

        // AV: t1b[b][q][h*64+d] = pb @ vs (out fp16)
        gemm_tc<64, false><<<dim3(1, Tq / 128, BHq), 256, SMEM_64F>>>(
            pb, vs, nullptr, t1b, Tq, Tq, Cq, Cq,
            (long)Hq * TT, TT, (long)Tq * Cq, Dq, (long)Tq * Cq, Dq, Hq,
            1.f, 0, 1);

        // output projection (out fp32) + add/LN
        gemm_tc<128, false><<<dim3(Cq / 128, Mq / 128, 1), 256, SMEM_128F>>>(
            t1b, wol, bol, t2, Cq, Cq, Cq, Cq, 0, 0, 0, 0, 0, 0, 1, 1.f, 0, 0);
        add_ln_kernel<<<Mq, 256>>>(x, t2, ln1g + (size_t)l * Cq, ln1b + (size_t)l * Cq, xb);

        // FFN
        gemm_tc<128, false><<<dim3(FFq / 128, Mq / 128, 1), 256, SMEM_128F>>>(
            xb, w1l, b1l, ffnb, Cq, Cq, FFq, FFq, 0, 0, 0, 0, 0, 0, 1, 1.f, 1, 1);
        gemm_tc<128, false><<<dim3(Cq / 128, Mq / 128, 1), 256, SMEM_128F>>>(
            ffnb, w2l, b2l, t2, FFq, FFq, Cq, Cq, 0, 0, 0, 0, 0, 0, 1, 1.f, 0, 0);
        add_ln_kernel<<<Mq, 256>>>(x, t2, ln2g + (size_t)l * Cq, ln2b + (size_t)l * Cq, xb);
    }

    // decoder: [4096,768] @ [768,32000] + bias (out fp32)
    gemm_tc<128, false><<<dim3(Vq / 128, Mq / 128, 1), 256, SMEM_128F>>>(
        xb, wdb, decb, out, Cq, Cq, Vq, Vq, 0, 0, 0, 0, 0, 0, 1, 1.f, 0, 0);
}

// round 5
// speedup vs baseline: 6.6579x; 1.0076x over previous
#include <cuda_runtime.h>
#include <cuda_fp16.h>
#include <cstdint>

#define Bq 8
#define Tq 512
#define Cq 768
#define Hq 12
#define Dq 64
#define Lq 12
#define Vq 32000
#define FFq 3072
#define Mq (Bq*Tq)          // 4096
#define BHq (Bq*Hq)         // 96
#define TT  (Tq*Tq)         // 262144
#define C3  (3*Cq)          // 2304

// ---------------- scratch (device globals) ----------------------------------
__device__ float g_x  [Mq*Cq];
__device__ float g_t2 [Mq*Cq];
__device__ float g_ps [4*BHq*Tq];

__device__ __half g_xb   [Mq*Cq];
__device__ __half g_qkvb [(size_t)Mq*C3];
__device__ __half g_pb   [(size_t)BHq*TT];
__device__ __half g_vs   [Mq*Cq];
__device__ __half g_t1b  [Mq*Cq];
__device__ __half g_ffnb [(size_t)Mq*FFq];
__device__ __half g_wqkv [(size_t)Lq*Cq*C3];
__device__ __half g_wob  [(size_t)Lq*Cq*Cq];
__device__ __half g_w1b  [(size_t)Lq*Cq*FFq];
__device__ __half g_w2b  [(size_t)Lq*FFq*Cq];
__device__ __half g_wdb  [(size_t)Cq*Vq];

// ---------------- small helpers ---------------------------------------------
__device__ __forceinline__ uint32_t s2u(const void* p) {
    return (uint32_t)__cvta_generic_to_shared(p);
}
__device__ __forceinline__ void cpa16(void* smem, const void* gmem) {
    uint32_t s = s2u(smem);
    asm volatile("cp.async.cg.shared.global [%0], [%1], 16;\n" :: "r"(s), "l"(gmem));
}
__device__ __forceinline__ void ldm_x4(uint32_t* r, uint32_t addr) {
    asm volatile("ldmatrix.sync.aligned.m8n8.x4.shared.b16 {%0,%1,%2,%3}, [%4];"
        : "=r"(r[0]), "=r"(r[1]), "=r"(r[2]), "=r"(r[3]) : "r"(addr));
}
__device__ __forceinline__ void ldm_x4_t(uint32_t* r, uint32_t addr) {
    asm volatile("ldmatrix.sync.aligned.m8n8.x4.trans.shared.b16 {%0,%1,%2,%3}, [%4];"
        : "=r"(r[0]), "=r"(r[1]), "=r"(r[2]), "=r"(r[3]) : "r"(addr));
}
__device__ __forceinline__ void mma16816(float* c, const uint32_t* a, uint32_t b0, uint32_t b1) {
    asm volatile(
        "mma.sync.aligned.m16n8k16.row.col.f32.f16.f16.f32 "
        "{%0,%1,%2,%3}, {%4,%5,%6,%7}, {%8,%9}, {%0,%1,%2,%3};"
        : "+f"(c[0]), "+f"(c[1]), "+f"(c[2]), "+f"(c[3])
        : "r"(a[0]), "r"(a[1]), "r"(a[2]), "r"(a[3]), "r"(b0), "r"(b1));
}

// ---------------- fp16 tensor-core GEMM (3-stage cp.async pipeline) ----------
// C[M,N] = alpha * A[M,K] * op(B) (+bias) (+relu). A/B fp16, C fp32 or fp16.
// BT=false: B is [K,N] row-major. BT=true: B is [N,K] row-major.
// EXPSUM (BN=128 only): C = fp16(exp(alpha*acc - 4)); per-block column partial
// sums written to psum[qtile*gridDim.z + z][bn..bn+127].
// BM=128, BK=32, 256 threads, warps 4x2, warp tile 32 x BN/2. Dynamic smem.
template<int BN, bool BT, bool EXPSUM>
__global__ void __launch_bounds__(256, 2)
gemm_tc(const __half* __restrict__ A, const __half* __restrict__ B,
        const float* __restrict__ bias, void* __restrict__ Cout,
        float* __restrict__ psum,
        int K, int lda, int ldb, int ldc,
        long sAo, long sAi, long sBo, long sBi, long sCo, long sCi, int zdiv,
        float alpha, int relu, int outhalf)
{
    extern __shared__ __half smem_dyn[];
    constexpr int ASIZE = 128 * 40;
    constexpr int BROWS = BT ? BN : 32;
    constexpr int BCOLS = BT ? 40 : (BN + 8);
    constexpr int BSIZE = BROWS * BCOLS;
    __half* Asm = smem_dyn;                 // [3][128][40]
    __half* Bsm = smem_dyn + 3 * ASIZE;     // [3][BROWS][BCOLS]

    const int zo = blockIdx.z / zdiv, zi = blockIdx.z - zo * zdiv;
    A += zo * sAo + zi * sAi;
    B += zo * sBo + zi * sBi;
    float* Cf  = (float*)Cout  + zo * sCo + zi * sCi;
    __half* Ch = (__half*)Cout + zo * sCo + zi * sCi;

    const int bm = blockIdx.y * 128;
    const int bn = blockIdx.x * BN;

    const int tid  = threadIdx.x;
    const int lane = tid & 31;
    const int warp = tid >> 5;
    const int wm   = warp & 3;
    const int wn   = warp >> 2;
    const int m_w  = wm * 32;
    const int n_w  = wn * (BN / 2);
    constexpr int NT8  = (BN / 2) / 8;
    constexpr int NT16 = (BN / 2) / 16;

    const __half* Ag = A + (long)bm * lda;
    const __half* Bg = BT ? (B + (long)bn * ldb) : (B + bn);

    float acc[2][NT8][4];
#pragma unroll
    for (int i = 0; i < 2; i++)
#pragma unroll
        for (int j = 0; j < NT8; j++)
#pragma unroll
            for (int q = 0; q < 4; q++) acc[i][j][q] = 0.f;

    auto stage = [&](int s, int k0) {
        __half* As = Asm + s * ASIZE;
        __half* Bs = Bsm + s * BSIZE;
#pragma unroll
        for (int i = 0; i < 2; i++) {
            int ci = tid + i * 256;
            int r = ci >> 2, kc = (ci & 3) << 3;
            cpa16(&As[r * 40 + kc], Ag + (long)r * lda + k0 + kc);
        }
        if (BT) {
            constexpr int IT = (BN * 4) / 256;
#pragma unroll
            for (int i = 0; i < IT; i++) {
                int ci = tid + i * 256;
                int r = ci >> 2, kc = (ci & 3) << 3;
                cpa16(&Bs[r * 40 + kc], Bg + (long)r * ldb + k0 + kc);
            }
        } else {
            constexpr int CH = BN / 8;
            constexpr int IT = (32 * CH) / 256;
#pragma unroll
            for (int i = 0; i < IT; i++) {
                int ci = tid + i * 256;
                int r = ci / CH, nc = (ci % CH) << 3;
                cpa16(&Bs[r * BCOLS + nc], Bg + (long)(k0 + r) * ldb + nc);
            }
        }
    };

    auto compute = [&](int s) {
        uint32_t aBase = s2u(Asm + s * ASIZE);
        uint32_t bBase = s2u(Bsm + s * BSIZE);
#pragma unroll
        for (int kk = 0; kk < 32; kk += 16) {
            uint32_t ar[2][4];
#pragma unroll
            for (int mt = 0; mt < 2; mt++) {
                uint32_t addr = aBase +
                    2u * ((m_w + mt * 16 + (lane & 15)) * 40 + kk + ((lane >> 4) << 3));
                ldm_x4(ar[mt], addr);
            }
            uint32_t br[NT16][4];
#pragma unroll
            for (int nt = 0; nt < NT16; nt++) {
                if (BT) {
                    uint32_t addr = bBase +
                        2u * ((n_w + nt * 16 + (lane & 15)) * 40 + kk + ((lane >> 4) << 3));
                    ldm_x4(br[nt], addr);
                } else {
                    uint32_t addr = bBase +
                        2u * ((kk + (lane & 15)) * BCOLS + n_w + nt * 16 + ((lane >> 4) << 3));
                    ldm_x4_t(br[nt], addr);
                }
            }
#pragma unroll
            for (int mt = 0; mt < 2; mt++)
#pragma unroll
                for (int n8 = 0; n8 < NT8; n8++) {
                    int nt = n8 >> 1, h = n8 & 1;
                    uint32_t b0, b1;
                    if (BT) { b0 = br[nt][h];     b1 = br[nt][2 + h];     }
                    else    { b0 = br[nt][h * 2]; b1 = br[nt][h * 2 + 1]; }
                    mma16816(acc[mt][n8], ar[mt], b0, b1);
                }
        }
    };

    const int ntile = K >> 5;
    stage(0, 0);
    asm volatile("cp.async.commit_group;");
    stage(1, 32);
    asm volatile("cp.async.commit_group;");
    for (int kt = 0; kt < ntile; kt++) {
        asm volatile("cp.async.wait_group 1;");
        __syncthreads();
        if (kt + 2 < ntile) stage((kt + 2) % 3, (kt + 2) << 5);
        asm volatile("cp.async.commit_group;");
        compute(kt % 3);
    }

    const int r0 = bm + m_w + (lane >> 2);
    const int c0 = bn + n_w + ((lane & 3) << 1);

    if (EXPSUM) {
        // write pb = exp(alpha*acc - 4) fp16; column partial sums -> psum
        float cs[NT8][2];
#pragma unroll
        for (int n8 = 0; n8 < NT8; n8++) { cs[n8][0] = 0.f; cs[n8][1] = 0.f; }
#pragma unroll
        for (int n8 = 0; n8 < NT8; n8++) {
            int c = c0 + n8 * 8;
#pragma unroll
            for (int mt = 0; mt < 2; mt++) {
#pragma unroll
                for (int hh = 0; hh < 2; hh++) {
                    int r = r0 + mt * 16 + hh * 8;
                    float v0 = __expf(fmaf(acc[mt][n8][hh * 2 + 0], alpha, -4.f));
                    float v1 = __expf(fmaf(acc[mt][n8][hh * 2 + 1], alpha, -4.f));
                    *reinterpret_cast<__half2*>(Ch + (long)r * ldc + c) =
                        __floats2half2_rn(v0, v1);
                    cs[n8][0] += v0; cs[n8][1] += v1;
                }
            }
        }
#pragma unroll
        for (int n8 = 0; n8 < NT8; n8++)
#pragma unroll
            for (int p = 0; p < 2; p++) {
                float v = cs[n8][p];
                v += __shfl_xor_sync(0xffffffffu, v, 4);
                v += __shfl_xor_sync(0xffffffffu, v, 8);
                v += __shfl_xor_sync(0xffffffffu, v, 16);
                cs[n8][p] = v;
            }
        __syncthreads();                       // smem reuse barrier
        float* sred = (float*)smem_dyn;        // [8 warps][64]
        if (lane < 4) {
#pragma unroll
            for (int n8 = 0; n8 < NT8; n8++) {
                sred[warp * 64 + n8 * 8 + lane * 2 + 0] = cs[n8][0];
                sred[warp * 64 + n8 * 8 + lane * 2 + 1] = cs[n8][1];
            }
        }
        __syncthreads();
        if (tid < 128) {
            int wn2 = tid >> 6, cin = tid & 63;
            float t = 0.f;
#pragma unroll
            for (int w2 = 0; w2 < 4; w2++) t += sred[(wn2 * 4 + w2) * 64 + cin];
            psum[((long)blockIdx.y * gridDim.z + blockIdx.z) * ldc + bn + tid] = t;
        }
        return;
    }

    // normal epilogue
#pragma unroll
    for (int n8 = 0; n8 < NT8; n8++) {
        int c = c0 + n8 * 8;
        float bb0 = 0.f, bb1 = 0.f;
        if (bias) { bb0 = __ldg(&bias[c]); bb1 = __ldg(&bias[c + 1]); }
#pragma unroll
        for (int mt = 0; mt < 2; mt++) {
#pragma unroll
            for (int hh = 0; hh < 2; hh++) {
                int r = r0 + mt * 16 + hh * 8;
                float v0 = acc[mt][n8][hh * 2 + 0] * alpha + bb0;
                float v1 = acc[mt][n8][hh * 2 + 1] * alpha + bb1;
                if (relu) { v0 = fmaxf(v0, 0.f); v1 = fmaxf(v1, 0.f); }
                if (outhalf) {
                    *reinterpret_cast<__half2*>(Ch + (long)r * ldc + c) =
                        __floats2half2_rn(v0, v1);
                } else {
                    *reinterpret_cast<float2*>(Cf + (long)r * ldc + c) = make_float2(v0, v1);
                }
            }
        }
    }
}

// smem sizes (bytes)
#define SMEM_128F (3*(128*40 + 32*136)*2)   // 56832
#define SMEM_128T (3*(128*40 + 128*40)*2)   // 61440
#define SMEM_64F  (3*(128*40 + 32*72)*2)    // 44544

// ---------------- conversions ------------------------------------------------
// W[l][h][c][d] -> Wt[l][c][coloff + h*64 + d]  (fp16, ld = 2304)
__global__ void qkv_tr_kernel(const float* __restrict__ W, __half* __restrict__ Wt, int coloff)
{
    long i = (long)blockIdx.x * blockDim.x + threadIdx.x;
    long idx = i * 4;
    if (idx >= (long)Lq * Hq * Cq * Dq) return;
    int d = idx & 63;
    long rest = idx >> 6;
    int c = rest % Cq;
    rest /= Cq;
    int h = rest % Hq;
    int l = rest / Hq;
    float4 v = *reinterpret_cast<const float4*>(&W[idx]);
    __half* o = &Wt[((long)l * Cq + c) * C3 + coloff + h * Dq + d];
    reinterpret_cast<__half2*>(o)[0] = __floats2half2_rn(v.x, v.y);
    reinterpret_cast<__half2*>(o)[1] = __floats2half2_rn(v.z, v.w);
}

// single mega f2h over Wo, W1, W2, dec
#define N0 1769472L
#define N1 7077888L
#define N2 7077888L
#define N3 6144000L
__global__ void f2h_all_kernel(const float* __restrict__ Wo, const float* __restrict__ W1,
                               const float* __restrict__ W2, const float* __restrict__ dec,
                               __half* __restrict__ wob, __half* __restrict__ w1b,
                               __half* __restrict__ w2b, __half* __restrict__ wdb)
{
    long i = (long)blockIdx.x * blockDim.x + threadIdx.x;
    const float* src; __half* dst; long j;
    if      (i < N0)            { src = Wo;  dst = wob; j = i; }
    else if (i < N0+N1)         { src = W1;  dst = w1b; j = i - N0; }
    else if (i < N0+N1+N2)      { src = W2;  dst = w2b; j = i - N0 - N1; }
    else if (i < N0+N1+N2+N3)   { src = dec; dst = wdb; j = i - N0 - N1 - N2; }
    else return;
    float4 v = reinterpret_cast<const float4*>(src)[j];
    reinterpret_cast<__half2*>(dst)[j * 2 + 0] = __floats2half2_rn(v.x, v.y);
    reinterpret_cast<__half2*>(dst)[j * 2 + 1] = __floats2half2_rn(v.z, v.w);
}

// ---------------- embed -------------------------------------------------------
__global__ void embed_kernel(const int* __restrict__ ids, const float* __restrict__ emb,
                             const float* __restrict__ pos,
                             float* __restrict__ x, __half* __restrict__ xb)
{
    int idx = blockIdx.x * blockDim.x + threadIdx.x;
    if (idx >= Mq * Cq) return;
    int m = idx / Cq, c = idx - m * Cq;
    int t = m & (Tq - 1);
    int tok = ids[m];
    float v = emb[(size_t)tok * Cq + c] + pos[(size_t)t * Cq + c];
    x[idx]  = v;
    xb[idx] = __float2half(v);
}

// vs[m][c] = V[m][c] / colsum  (V = qkv cols 1536..2303; colsum from 4 partials)
__global__ void vscale_kernel(const __half* __restrict__ qkv,
                              const float* __restrict__ ps, __half* __restrict__ vs)
{
    int idx = blockIdx.x * blockDim.x + threadIdx.x;  // half2 units
    if (idx >= Mq * Cq / 2) return;
    int c2 = idx % (Cq / 2);
    int m  = idx / (Cq / 2);
    int c  = c2 * 2;
    int b  = m >> 9, t = m & 511, h = c >> 6;
    long si = (((long)b * Hq + h) << 9) + t;
    float s = ps[si] + ps[(long)BHq * Tq + si]
            + ps[2L * BHq * Tq + si] + ps[3L * BHq * Tq + si];
    float r = 1.f / s;
    __half2 v = *reinterpret_cast<const __half2*>(&qkv[(long)m * C3 + 1536 + c]);
    float2 f = __half22float2(v);
    *reinterpret_cast<__half2*>(&vs[(long)m * Cq + c]) = __floats2half2_rn(f.x * r, f.y * r);
}

// ---------------- residual add + layernorm ------------------------------------
__device__ __forceinline__ float block_sum768(float val, float* sh)
{
#pragma unroll
    for (int o = 16; o > 0; o >>= 1) val += __shfl_xor_sync(0xffffffffu, val, o);
    __syncthreads();
    if ((threadIdx.x & 31) == 0) sh[threadIdx.x >> 5] = val;
    __syncthreads();
    float tot = 0.f;
#pragma unroll
    for (int i = 0; i < 8; i++) tot += sh[i];
    return tot;
}

__global__ void __launch_bounds__(256)
add_ln_kernel(float* __restrict__ x, const float* __restrict__ y,
              const float* __restrict__ g, const float* __restrict__ bta,
              __half* __restrict__ xb)
{
    __shared__ float sh[8];
    long row = blockIdx.x;
    int tid = threadIdx.x;
    float v[3];
    float s = 0.f;
#pragma unroll
    for (int j = 0; j < 3; j++) {
        int c = tid + j * 256;
        v[j] = x[row * Cq + c] + y[row * Cq + c];
        s += v[j];
    }
    float mu = block_sum768(s, sh) * (1.f / Cq);
    float s2 = 0.f;
#pragma unroll
    for (int j = 0; j < 3; j++) { float d = v[j] - mu; s2 += d * d; }
    float var = block_sum768(s2, sh) * (1.f / Cq);
    float rstd = rsqrtf(var + 1e-5f);
#pragma unroll
    for (int j = 0; j < 3; j++) {
        int c = tid + j * 256;
        float o = (v[j] - mu) * rstd * g[c] + bta[c];
        x[row * Cq + c]  = o;
        xb[row * Cq + c] = __float2half(o);
    }
}

// ---------------- launch -------------------------------------------------------
extern "C" void kernel_launch(void* const* d_in, const int* in_sizes, int n_in,
                              void* d_out, int out_size)
{
    const int*   ids  = (const int*)  d_in[0];
    const float* emb  = (const float*)d_in[1];
    const float* pos  = (const float*)d_in[2];
    const float* Wq   = (const float*)d_in[3];
    const float* Wk   = (const float*)d_in[4];
    const float* Wv   = (const float*)d_in[5];
    const float* Wo   = (const float*)d_in[6];
    const float* bo   = (const float*)d_in[7];
    const float* ln1g = (const float*)d_in[8];
    const float* ln1b = (const float*)d_in[9];
    const float* W1   = (const float*)d_in[10];
    const float* b1   = (const float*)d_in[11];
    const float* W2   = (const float*)d_in[12];
    const float* b2   = (const float*)d_in[13];
    const float* ln2g = (const float*)d_in[14];
    const float* ln2b = (const float*)d_in[15];
    const float* decW = (const float*)d_in[16];
    const float* decb = (const float*)d_in[17];
    float* out = (float*)d_out;

    cudaFuncSetAttribute(gemm_tc<128, false, false>,
        cudaFuncAttributeMaxDynamicSharedMemorySize, SMEM_128F);
    cudaFuncSetAttribute(gemm_tc<128, true, true>,
        cudaFuncAttributeMaxDynamicSharedMemorySize, SMEM_128T);
    cudaFuncSetAttribute(gemm_tc<64, false, false>,
        cudaFuncAttributeMaxDynamicSharedMemorySize, SMEM_64F);

    float *x, *t2, *ps;
    __half *xb, *qkvb, *pb, *vs, *t1b, *ffnb;
    __half *wqkv, *wob, *w1b, *w2b, *wdb;
    cudaGetSymbolAddress((void**)&x,    g_x);
    cudaGetSymbolAddress((void**)&t2,   g_t2);
    cudaGetSymbolAddress((void**)&ps,   g_ps);
    cudaGetSymbolAddress((void**)&xb,   g_xb);
    cudaGetSymbolAddress((void**)&qkvb, g_qkvb);
    cudaGetSymbolAddress((void**)&pb,   g_pb);
    cudaGetSymbolAddress((void**)&vs,   g_vs);
    cudaGetSymbolAddress((void**)&t1b,  g_t1b);
    cudaGetSymbolAddress((void**)&ffnb, g_ffnb);
    cudaGetSymbolAddress((void**)&wqkv, g_wqkv);
    cudaGetSymbolAddress((void**)&wob,  g_wob);
    cudaGetSymbolAddress((void**)&w1b,  g_w1b);
    cudaGetSymbolAddress((void**)&w2b,  g_w2b);
    cudaGetSymbolAddress((void**)&wdb,  g_wdb);

    // weight conversions: 4 launches, then embed, then QKV GEMM (= launch #5 for ncu)
    {
        long n = (long)Lq * Cq * Cq;
        int  bl = 256;
        long g4 = (n / 4 + bl - 1) / bl;
        qkv_tr_kernel<<<(unsigned)g4, bl>>>(Wq, wqkv, 0);
        qkv_tr_kernel<<<(unsigned)g4, bl>>>(Wk, wqkv, 768);
        qkv_tr_kernel<<<(unsigned)g4, bl>>>(Wv, wqkv, 1536);
        long ntot = N0 + N1 + N2 + N3;
        f2h_all_kernel<<<(unsigned)((ntot + bl - 1) / bl), bl>>>(
            Wo, W1, W2, decW, wob, w1b, w2b, wdb);
    }

    embed_kernel<<<(Mq * Cq + 255) / 256, 256>>>(ids, emb, pos, x, xb);

    for (int l = 0; l < Lq; l++) {
        const __half* wqkvl = wqkv + (size_t)l * Cq * C3;
        const __half* wol   = wob  + (size_t)l * Cq * Cq;
        const __half* w1l   = w1b  + (size_t)l * Cq * FFq;
        const __half* w2l   = w2b  + (size_t)l * FFq * Cq;
        const float* bol = bo + (size_t)l * Cq;
        const float* b1l = b1 + (size_t)l * FFq;
        const float* b2l = b2 + (size_t)l * Cq;

        // fused QKV: [4096,768] @ [768,2304] -> qkvb fp16
        gemm_tc<128, false, false><<<dim3(C3 / 128, Mq / 128, 1), 256, SMEM_128F>>>(
            xb, wqkvl, nullptr, qkvb, nullptr,
            Cq, Cq, C3, C3, 0, 0, 0, 0, 0, 0, 1, 1.f, 0, 1);

        // scores + exp + column partial sums: pb = exp(0.125*QK^T - 4)
        gemm_tc<128, true, true><<<dim3(Tq / 128, Tq / 128, BHq), 256, SMEM_128T>>>(
            qkvb, qkvb + 768, nullptr, pb, ps,
            Dq, C3, C3, Tq,
            (long)Tq * C3, Dq, (long)Tq * C3, Dq, (long)Hq * TT, TT, Hq,
            0.125f, 0, 1);

        // vs = V / colsum
        vscale_kernel<<<(Mq * Cq / 2 + 255) / 256, 256>>>(qkvb, ps, vs);

        // AV: t1b[b][q][h*64+d] = pb @ vs (out fp16)
        gemm_tc<64, false, false><<<dim3(1, Tq / 128, BHq), 256, SMEM_64F>>>(
            pb, vs, nullptr, t1b, nullptr,
            Tq, Tq, Cq, Cq,
            (long)Hq * TT, TT, (long)Tq * Cq, Dq, (long)Tq * Cq, Dq, Hq,
            1.f, 0, 1);

        // output projection (out fp32) + add/LN
        gemm_tc<128, false, false><<<dim3(Cq / 128, Mq / 128, 1), 256, SMEM_128F>>>(
            t1b, wol, bol, t2, nullptr,
            Cq, Cq, Cq, Cq, 0, 0, 0, 0, 0, 0, 1, 1.f, 0, 0);
        add_ln_kernel<<<Mq, 256>>>(x, t2, ln1g + (size_t)l * Cq, ln1b + (size_t)l * Cq, xb);

        // FFN
        gemm_tc<128, false, false><<<dim3(FFq / 128, Mq / 128, 1), 256, SMEM_128F>>>(
            xb, w1l, b1l, ffnb, nullptr,
            Cq, Cq, FFq, FFq, 0, 0, 0, 0, 0, 0, 1, 1.f, 1, 1);
        gemm_tc<128, false, false><<<dim3(Cq / 128, Mq / 128, 1), 256, SMEM_128F>>>(
            ffnb, w2l, b2l, t2, nullptr,
            FFq, FFq, Cq, Cq, 0, 0, 0, 0, 0, 0, 1, 1.f, 0, 0);
        add_ln_kernel<<<Mq, 256>>>(x, t2, ln2g + (size_t)l * Cq, ln2b + (size_t)l * Cq, xb);
    }

    // decoder: [4096,768] @ [768,32000] + bias (out fp32)
    gemm_tc<128, false, false><<<dim3(Vq / 128, Mq / 128, 1), 256, SMEM_128F>>>(
        xb, wdb, decb, out, nullptr,
        Cq, Cq, Vq, Vq, 0, 0, 0, 0, 0, 0, 1, 1.f, 0, 0);
}